// round 8
// baseline (speedup 1.0000x reference)
#include <cuda_runtime.h>
#include <cuda_bf16.h>

// SHEmbed, quad-cooperative gather with interleaved 64B chunks.
// 4 lanes per ray; lane p loads float4s {p, p+4, p+8} of the 192B record so each
// LDG.128's quad covers one 64B-aligned chunk -> 1 L1 line per instr per ray
// (3 wavefronts/ray total, vs 6 for contiguous slices).
// Each lane accumulates partial (r,g,b) using its 6 relevant basis weights,
// quad-butterfly-reduces, lane p<3 writes channel p.

#define SH_W 1024

__global__ __launch_bounds__(256)
void SHEmbed_kernel(const int* __restrict__ yi,
                    const int* __restrict__ xi,
                    const float* __restrict__ dirs,
                    const float4* __restrict__ sh,   // sh_data viewed as float4[H*W*12]
                    float* __restrict__ out,
                    int n)
{
    int t = blockIdx.x * blockDim.x + threadIdx.x;
    int r = t >> 2;          // ray index
    int p = t & 3;           // quad lane
    if (r >= n) return;

    // ---- issue all loads up front ----
    int yv = __ldg(yi + r);
    int xv = __ldg(xi + r);
    float dx = __ldg(dirs + 3 * r + 0);
    float dy = __ldg(dirs + 3 * r + 1);
    float dz = __ldg(dirs + 3 * r + 2);

    unsigned base = ((unsigned)yv * SH_W + (unsigned)xv) * 12u + (unsigned)p;
    float4 v0 = __ldg(sh + base + 0);   // record floats [4p   .. 4p+3 ]
    float4 v1 = __ldg(sh + base + 4);   // record floats [16+4p..16+4p+3]
    float4 v2 = __ldg(sh + base + 8);   // record floats [32+4p..32+4p+3]

    // ---- unit direction (overlaps gather latency) ----
    float rinv = rsqrtf(dx * dx + dy * dy + dz * dz + 1e-28f);
    float nx = dx * rinv, ny = dy * rinv, nz = dz * rinv;

    float xx = nx * nx, yy = ny * ny, zz = nz * nz;
    float xy = nx * ny, yz = ny * nz, xz = nx * nz;

    // Global float index g = 16*chunk + 4p + i ; coeff j = g/3, channel = g%3.
    // Each lane p needs only 6 of the 16 basis weights (hardcoded below).
    float cr = 0.0f, cg = 0.0f, cb = 0.0f;

    switch (p) {
    case 0: {   // g: 0..3 | 16..19 | 32..35  -> coeffs {0,1,5,6,10,11}
        float b0  =  0.28209479177387814f;
        float b1  = -0.4886025119029199f * ny;
        float b5  = -1.0925484305920792f * yz;
        float b6  =  0.31539156525252005f * (3.0f * zz - 1.0f);
        float b10 =  2.890611442640554f  * xy * nz;
        float b11 = -0.4570457994644658f * ny * (5.0f * zz - 1.0f);
        cr += b0  * v0.x;  cg += b0  * v0.y;  cb += b0  * v0.z;  cr += b1  * v0.w;
        cg += b5  * v1.x;  cb += b5  * v1.y;  cr += b6  * v1.z;  cg += b6  * v1.w;
        cb += b10 * v2.x;  cr += b11 * v2.y;  cg += b11 * v2.z;  cb += b11 * v2.w;
        break;
    }
    case 1: {   // g: 4..7 | 20..23 | 36..39  -> coeffs {1,2,6,7,12,13}
        float b1  = -0.4886025119029199f * ny;
        float b2  =  0.4886025119029199f * nz;
        float b6  =  0.31539156525252005f * (3.0f * zz - 1.0f);
        float b7  = -1.0925484305920792f * xz;
        float b12 =  0.3731763325901154f * nz * (5.0f * zz - 3.0f);
        float b13 = -0.4570457994644658f * nx * (5.0f * zz - 1.0f);
        cg += b1  * v0.x;  cb += b1  * v0.y;  cr += b2  * v0.z;  cg += b2  * v0.w;
        cb += b6  * v1.x;  cr += b7  * v1.y;  cg += b7  * v1.z;  cb += b7  * v1.w;
        cr += b12 * v2.x;  cg += b12 * v2.y;  cb += b12 * v2.z;  cr += b13 * v2.w;
        break;
    }
    case 2: {   // g: 8..11 | 24..27 | 40..43 -> coeffs {2,3,8,9,13,14}
        float b2  =  0.4886025119029199f * nz;
        float b3  = -0.4886025119029199f * nx;
        float b8  =  0.5462742152960396f * (xx - yy);
        float b9  = -0.5900435899266435f * ny * (3.0f * xx - yy);
        float b13 = -0.4570457994644658f * nx * (5.0f * zz - 1.0f);
        float b14 =  1.4453057213202769f * nz * (xx - yy);
        cb += b2  * v0.x;  cr += b3  * v0.y;  cg += b3  * v0.z;  cb += b3  * v0.w;
        cr += b8  * v1.x;  cg += b8  * v1.y;  cb += b8  * v1.z;  cr += b9  * v1.w;
        cg += b13 * v2.x;  cb += b13 * v2.y;  cr += b14 * v2.z;  cg += b14 * v2.w;
        break;
    }
    default: {  // g: 12..15 | 28..31 | 44..47 -> coeffs {4,5,9,10,14,15}
        float b4  =  1.0925484305920792f * xy;
        float b5  = -1.0925484305920792f * yz;
        float b9  = -0.5900435899266435f * ny * (3.0f * xx - yy);
        float b10 =  2.890611442640554f  * xy * nz;
        float b14 =  1.4453057213202769f * nz * (xx - yy);
        float b15 = -0.5900435899266435f * nx * (xx - 3.0f * yy);
        cr += b4  * v0.x;  cg += b4  * v0.y;  cb += b4  * v0.z;  cr += b5  * v0.w;
        cg += b9  * v1.x;  cb += b9  * v1.y;  cr += b10 * v1.z;  cg += b10 * v1.w;
        cb += b14 * v2.x;  cr += b15 * v2.y;  cg += b15 * v2.z;  cb += b15 * v2.w;
        break;
    }
    }

    // ---- quad reduction (lanes p=0..3 of the same ray) ----
    const unsigned m = 0xffffffffu;
    cr += __shfl_xor_sync(m, cr, 1);
    cr += __shfl_xor_sync(m, cr, 2);
    cg += __shfl_xor_sync(m, cg, 1);
    cg += __shfl_xor_sync(m, cg, 2);
    cb += __shfl_xor_sync(m, cb, 1);
    cb += __shfl_xor_sync(m, cb, 2);

    // ---- clamp + store: lane p<3 writes channel p ----
    if (p < 3) {
        float v = (p == 0) ? cr : (p == 1) ? cg : cb;
        out[3 * r + p] = fminf(fmaxf(v, 0.0f), 1.0f);
    }
}

extern "C" void kernel_launch(void* const* d_in, const int* in_sizes, int n_in,
                              void* d_out, int out_size)
{
    const int*    y    = (const int*)d_in[0];
    const int*    x    = (const int*)d_in[1];
    const float*  dirs = (const float*)d_in[2];
    const float4* sh   = (const float4*)d_in[3];
    float*        out  = (float*)d_out;

    int n = in_sizes[0];
    int threads = 256;
    long long total = 4LL * n;
    int blocks = (int)((total + threads - 1) / threads);
    SHEmbed_kernel<<<blocks, threads>>>(y, x, dirs, sh, out, n);
}

// round 9
// speedup vs baseline: 1.0585x; 1.0585x over previous
#include <cuda_runtime.h>
#include <cuda_bf16.h>

// SHEmbed, quad-cooperative gather (contiguous 48B slices), 2 rays per thread.
// 4 lanes per ray; lane p loads float4s 3p..3p+2 (coeffs 4p..4p+3) of each ray's
// 192B record. All loads for both rays issued up front (MLP ~ 10/thread).
// One switch(p) covers both rays' weight+dot code (divergence paid once).
// Quad-butterfly reduction; lane p<3 writes channel p of both rays.

#define SH_W 1024

__device__ __forceinline__ float clamp01(float v) {
    return fminf(fmaxf(v, 0.0f), 1.0f);
}

__global__ __launch_bounds__(256)
void SHEmbed_kernel(const int* __restrict__ yi,
                    const int* __restrict__ xi,
                    const float* __restrict__ dirs,
                    const float4* __restrict__ sh,   // sh_data viewed as float4[H*W*12]
                    float* __restrict__ out,
                    int n)
{
    int t = blockIdx.x * blockDim.x + threadIdx.x;
    int q = t >> 2;          // ray-pair index
    int p = t & 3;           // quad lane: coefficient group 4p..4p+3
    int r0 = q * 2;
    if (r0 >= n) return;
    int r1 = (r0 + 1 < n) ? (r0 + 1) : r0;   // clamp tail (n is even in practice)

    // ---- front-batch ALL independent loads for both rays ----
    int y0 = __ldg(yi + r0), x0 = __ldg(xi + r0);
    int y1 = __ldg(yi + r1), x1 = __ldg(xi + r1);

    float dx0 = __ldg(dirs + 3 * r0 + 0);
    float dy0 = __ldg(dirs + 3 * r0 + 1);
    float dz0 = __ldg(dirs + 3 * r0 + 2);
    float dx1 = __ldg(dirs + 3 * r1 + 0);
    float dy1 = __ldg(dirs + 3 * r1 + 1);
    float dz1 = __ldg(dirs + 3 * r1 + 2);

    unsigned b0i = ((unsigned)y0 * SH_W + (unsigned)x0) * 12u + (unsigned)(3 * p);
    unsigned b1i = ((unsigned)y1 * SH_W + (unsigned)x1) * 12u + (unsigned)(3 * p);

    float4 a0 = __ldg(sh + b0i + 0);
    float4 a1 = __ldg(sh + b0i + 1);
    float4 a2 = __ldg(sh + b0i + 2);
    float4 c0 = __ldg(sh + b1i + 0);
    float4 c1 = __ldg(sh + b1i + 1);
    float4 c2 = __ldg(sh + b1i + 2);

    // ---- unit directions (overlap gather latency) ----
    float ri0 = rsqrtf(dx0 * dx0 + dy0 * dy0 + dz0 * dz0 + 1e-28f);
    float nx0 = dx0 * ri0, ny0 = dy0 * ri0, nz0 = dz0 * ri0;
    float ri1 = rsqrtf(dx1 * dx1 + dy1 * dy1 + dz1 * dz1 + 1e-28f);
    float nx1 = dx1 * ri1, ny1 = dy1 * ri1, nz1 = dz1 * ri1;

    float xx0 = nx0 * nx0, yy0 = ny0 * ny0, zz0 = nz0 * nz0;
    float xy0 = nx0 * ny0, yz0 = ny0 * nz0, xz0 = nx0 * nz0;
    float xx1 = nx1 * nx1, yy1 = ny1 * ny1, zz1 = nz1 * nz1;
    float xy1 = nx1 * ny1, yz1 = ny1 * nz1, xz1 = nx1 * nz1;

    // ---- per-lane weights for coeffs 4p..4p+3, both rays ----
    float w00, w01, w02, w03;   // ray0
    float w10, w11, w12, w13;   // ray1
    switch (p) {
    case 0:
        w00 =  0.28209479177387814f;
        w01 = -0.4886025119029199f * ny0;
        w02 =  0.4886025119029199f * nz0;
        w03 = -0.4886025119029199f * nx0;
        w10 =  0.28209479177387814f;
        w11 = -0.4886025119029199f * ny1;
        w12 =  0.4886025119029199f * nz1;
        w13 = -0.4886025119029199f * nx1;
        break;
    case 1:
        w00 =  1.0925484305920792f * xy0;
        w01 = -1.0925484305920792f * yz0;
        w02 =  0.31539156525252005f * (3.0f * zz0 - 1.0f);
        w03 = -1.0925484305920792f * xz0;
        w10 =  1.0925484305920792f * xy1;
        w11 = -1.0925484305920792f * yz1;
        w12 =  0.31539156525252005f * (3.0f * zz1 - 1.0f);
        w13 = -1.0925484305920792f * xz1;
        break;
    case 2:
        w00 =  0.5462742152960396f * (xx0 - yy0);
        w01 = -0.5900435899266435f * ny0 * (3.0f * xx0 - yy0);
        w02 =  2.890611442640554f  * xy0 * nz0;
        w03 = -0.4570457994644658f * ny0 * (5.0f * zz0 - 1.0f);
        w10 =  0.5462742152960396f * (xx1 - yy1);
        w11 = -0.5900435899266435f * ny1 * (3.0f * xx1 - yy1);
        w12 =  2.890611442640554f  * xy1 * nz1;
        w13 = -0.4570457994644658f * ny1 * (5.0f * zz1 - 1.0f);
        break;
    default:
        w00 =  0.3731763325901154f * nz0 * (5.0f * zz0 - 3.0f);
        w01 = -0.4570457994644658f * nx0 * (5.0f * zz0 - 1.0f);
        w02 =  1.4453057213202769f * nz0 * (xx0 - yy0);
        w03 = -0.5900435899266435f * nx0 * (xx0 - 3.0f * yy0);
        w10 =  0.3731763325901154f * nz1 * (5.0f * zz1 - 3.0f);
        w11 = -0.4570457994644658f * nx1 * (5.0f * zz1 - 1.0f);
        w12 =  1.4453057213202769f * nz1 * (xx1 - yy1);
        w13 = -0.5900435899266435f * nx1 * (xx1 - 3.0f * yy1);
        break;
    }

    // ---- partial dots (chunk layout: {c0r,c0g,c0b,c1r}{c1g,c1b,c2r,c2g}{c2b,c3r,c3g,c3b}) ----
    float cr0 = w00 * a0.x + w01 * a0.w + w02 * a1.z + w03 * a2.y;
    float cg0 = w00 * a0.y + w01 * a1.x + w02 * a1.w + w03 * a2.z;
    float cb0 = w00 * a0.z + w01 * a1.y + w02 * a2.x + w03 * a2.w;
    float cr1 = w10 * c0.x + w11 * c0.w + w12 * c1.z + w13 * c2.y;
    float cg1 = w10 * c0.y + w11 * c1.x + w12 * c1.w + w13 * c2.z;
    float cb1 = w10 * c0.z + w11 * c1.y + w12 * c2.x + w13 * c2.w;

    // ---- quad reductions ----
    const unsigned m = 0xffffffffu;
    cr0 += __shfl_xor_sync(m, cr0, 1);  cr0 += __shfl_xor_sync(m, cr0, 2);
    cg0 += __shfl_xor_sync(m, cg0, 1);  cg0 += __shfl_xor_sync(m, cg0, 2);
    cb0 += __shfl_xor_sync(m, cb0, 1);  cb0 += __shfl_xor_sync(m, cb0, 2);
    cr1 += __shfl_xor_sync(m, cr1, 1);  cr1 += __shfl_xor_sync(m, cr1, 2);
    cg1 += __shfl_xor_sync(m, cg1, 1);  cg1 += __shfl_xor_sync(m, cg1, 2);
    cb1 += __shfl_xor_sync(m, cb1, 1);  cb1 += __shfl_xor_sync(m, cb1, 2);

    // ---- clamp + store: lane p<3 writes channel p of each ray ----
    if (p < 3) {
        float v0s = (p == 0) ? cr0 : (p == 1) ? cg0 : cb0;
        out[3 * r0 + p] = clamp01(v0s);
        if (r0 + 1 < n) {
            float v1s = (p == 0) ? cr1 : (p == 1) ? cg1 : cb1;
            out[3 * r1 + p] = clamp01(v1s);
        }
    }
}

extern "C" void kernel_launch(void* const* d_in, const int* in_sizes, int n_in,
                              void* d_out, int out_size)
{
    const int*    y    = (const int*)d_in[0];
    const int*    x    = (const int*)d_in[1];
    const float*  dirs = (const float*)d_in[2];
    const float4* sh   = (const float4*)d_in[3];
    float*        out  = (float*)d_out;

    int n = in_sizes[0];
    int threads = 256;
    long long pairs = ((long long)n + 1) / 2;
    long long total = 4LL * pairs;
    int blocks = (int)((total + threads - 1) / threads);
    SHEmbed_kernel<<<blocks, threads>>>(y, x, dirs, sh, out, n);
}

// round 14
// speedup vs baseline: 1.1156x; 1.0539x over previous
#include <cuda_runtime.h>
#include <cuda_bf16.h>

// SHEmbed, quad-cooperative gather (contiguous 48B slices), 2 rays per thread.
// L2 residency via createpolicy + ld.global.nc.L2::cache_hint (evict_last) on the
// table gather; streaming arrays use evict-first (__ldcs/__stcs).

#define SH_W 1024

__device__ __forceinline__ float clamp01(float v) {
    return fminf(fmaxf(v, 0.0f), 1.0f);
}

__device__ __forceinline__ float4 ldg_keep(const float4* p, unsigned long long pol) {
    float4 v;
    asm("ld.global.nc.L2::cache_hint.v4.f32 {%0,%1,%2,%3}, [%4], %5;"
        : "=f"(v.x), "=f"(v.y), "=f"(v.z), "=f"(v.w) : "l"(p), "l"(pol));
    return v;
}

__global__ __launch_bounds__(256)
void SHEmbed_kernel(const int* __restrict__ yi,
                    const int* __restrict__ xi,
                    const float* __restrict__ dirs,
                    const float4* __restrict__ sh,   // sh_data viewed as float4[H*W*12]
                    float* __restrict__ out,
                    int n)
{
    int t = blockIdx.x * blockDim.x + threadIdx.x;
    int q = t >> 2;          // ray-pair index
    int p = t & 3;           // quad lane: coefficient group 4p..4p+3
    int r0 = q * 2;
    if (r0 >= n) return;
    int r1 = (r0 + 1 < n) ? (r0 + 1) : r0;   // clamp tail

    unsigned long long pol;
    asm("createpolicy.fractional.L2::evict_last.b64 %0, 1.0;" : "=l"(pol));

    // ---- front-batch ALL independent loads for both rays (streaming: evict-first) ----
    int y0 = __ldcs(yi + r0), x0 = __ldcs(xi + r0);
    int y1 = __ldcs(yi + r1), x1 = __ldcs(xi + r1);

    float dx0 = __ldcs(dirs + 3 * r0 + 0);
    float dy0 = __ldcs(dirs + 3 * r0 + 1);
    float dz0 = __ldcs(dirs + 3 * r0 + 2);
    float dx1 = __ldcs(dirs + 3 * r1 + 0);
    float dy1 = __ldcs(dirs + 3 * r1 + 1);
    float dz1 = __ldcs(dirs + 3 * r1 + 2);

    unsigned b0i = ((unsigned)y0 * SH_W + (unsigned)x0) * 12u + (unsigned)(3 * p);
    unsigned b1i = ((unsigned)y1 * SH_W + (unsigned)x1) * 12u + (unsigned)(3 * p);

    // ---- gather: keep in L2 for duplicate-record reuse ----
    float4 a0 = ldg_keep(sh + b0i + 0, pol);
    float4 a1 = ldg_keep(sh + b0i + 1, pol);
    float4 a2 = ldg_keep(sh + b0i + 2, pol);
    float4 c0 = ldg_keep(sh + b1i + 0, pol);
    float4 c1 = ldg_keep(sh + b1i + 1, pol);
    float4 c2 = ldg_keep(sh + b1i + 2, pol);

    // ---- unit directions (overlap gather latency) ----
    float ri0 = rsqrtf(dx0 * dx0 + dy0 * dy0 + dz0 * dz0 + 1e-28f);
    float nx0 = dx0 * ri0, ny0 = dy0 * ri0, nz0 = dz0 * ri0;
    float ri1 = rsqrtf(dx1 * dx1 + dy1 * dy1 + dz1 * dz1 + 1e-28f);
    float nx1 = dx1 * ri1, ny1 = dy1 * ri1, nz1 = dz1 * ri1;

    float xx0 = nx0 * nx0, yy0 = ny0 * ny0, zz0 = nz0 * nz0;
    float xy0 = nx0 * ny0, yz0 = ny0 * nz0, xz0 = nx0 * nz0;
    float xx1 = nx1 * nx1, yy1 = ny1 * ny1, zz1 = nz1 * nz1;
    float xy1 = nx1 * ny1, yz1 = ny1 * nz1, xz1 = nx1 * nz1;

    // ---- per-lane weights for coeffs 4p..4p+3, both rays ----
    float w00, w01, w02, w03;   // ray0
    float w10, w11, w12, w13;   // ray1
    switch (p) {
    case 0:
        w00 =  0.28209479177387814f;
        w01 = -0.4886025119029199f * ny0;
        w02 =  0.4886025119029199f * nz0;
        w03 = -0.4886025119029199f * nx0;
        w10 =  0.28209479177387814f;
        w11 = -0.4886025119029199f * ny1;
        w12 =  0.4886025119029199f * nz1;
        w13 = -0.4886025119029199f * nx1;
        break;
    case 1:
        w00 =  1.0925484305920792f * xy0;
        w01 = -1.0925484305920792f * yz0;
        w02 =  0.31539156525252005f * (3.0f * zz0 - 1.0f);
        w03 = -1.0925484305920792f * xz0;
        w10 =  1.0925484305920792f * xy1;
        w11 = -1.0925484305920792f * yz1;
        w12 =  0.31539156525252005f * (3.0f * zz1 - 1.0f);
        w13 = -1.0925484305920792f * xz1;
        break;
    case 2:
        w00 =  0.5462742152960396f * (xx0 - yy0);
        w01 = -0.5900435899266435f * ny0 * (3.0f * xx0 - yy0);
        w02 =  2.890611442640554f  * xy0 * nz0;
        w03 = -0.4570457994644658f * ny0 * (5.0f * zz0 - 1.0f);
        w10 =  0.5462742152960396f * (xx1 - yy1);
        w11 = -0.5900435899266435f * ny1 * (3.0f * xx1 - yy1);
        w12 =  2.890611442640554f  * xy1 * nz1;
        w13 = -0.4570457994644658f * ny1 * (5.0f * zz1 - 1.0f);
        break;
    default:
        w00 =  0.3731763325901154f * nz0 * (5.0f * zz0 - 3.0f);
        w01 = -0.4570457994644658f * nx0 * (5.0f * zz0 - 1.0f);
        w02 =  1.4453057213202769f * nz0 * (xx0 - yy0);
        w03 = -0.5900435899266435f * nx0 * (xx0 - 3.0f * yy0);
        w10 =  0.3731763325901154f * nz1 * (5.0f * zz1 - 3.0f);
        w11 = -0.4570457994644658f * nx1 * (5.0f * zz1 - 1.0f);
        w12 =  1.4453057213202769f * nz1 * (xx1 - yy1);
        w13 = -0.5900435899266435f * nx1 * (xx1 - 3.0f * yy1);
        break;
    }

    // ---- partial dots (chunk layout: {c0r,c0g,c0b,c1r}{c1g,c1b,c2r,c2g}{c2b,c3r,c3g,c3b}) ----
    float cr0 = w00 * a0.x + w01 * a0.w + w02 * a1.z + w03 * a2.y;
    float cg0 = w00 * a0.y + w01 * a1.x + w02 * a1.w + w03 * a2.z;
    float cb0 = w00 * a0.z + w01 * a1.y + w02 * a2.x + w03 * a2.w;
    float cr1 = w10 * c0.x + w11 * c0.w + w12 * c1.z + w13 * c2.y;
    float cg1 = w10 * c0.y + w11 * c1.x + w12 * c1.w + w13 * c2.z;
    float cb1 = w10 * c0.z + w11 * c1.y + w12 * c2.x + w13 * c2.w;

    // ---- quad reductions ----
    const unsigned m = 0xffffffffu;
    cr0 += __shfl_xor_sync(m, cr0, 1);  cr0 += __shfl_xor_sync(m, cr0, 2);
    cg0 += __shfl_xor_sync(m, cg0, 1);  cg0 += __shfl_xor_sync(m, cg0, 2);
    cb0 += __shfl_xor_sync(m, cb0, 1);  cb0 += __shfl_xor_sync(m, cb0, 2);
    cr1 += __shfl_xor_sync(m, cr1, 1);  cr1 += __shfl_xor_sync(m, cr1, 2);
    cg1 += __shfl_xor_sync(m, cg1, 1);  cg1 += __shfl_xor_sync(m, cg1, 2);
    cb1 += __shfl_xor_sync(m, cb1, 1);  cb1 += __shfl_xor_sync(m, cb1, 2);

    // ---- clamp + store (streaming, evict-first): lane p<3 writes channel p ----
    if (p < 3) {
        float v0s = (p == 0) ? cr0 : (p == 1) ? cg0 : cb0;
        __stcs(out + 3 * r0 + p, clamp01(v0s));
        if (r0 + 1 < n) {
            float v1s = (p == 0) ? cr1 : (p == 1) ? cg1 : cb1;
            __stcs(out + 3 * r1 + p, clamp01(v1s));
        }
    }
}

extern "C" void kernel_launch(void* const* d_in, const int* in_sizes, int n_in,
                              void* d_out, int out_size)
{
    const int*    y    = (const int*)d_in[0];
    const int*    x    = (const int*)d_in[1];
    const float*  dirs = (const float*)d_in[2];
    const float4* sh   = (const float4*)d_in[3];
    float*        out  = (float*)d_out;

    int n = in_sizes[0];
    int threads = 256;
    long long pairs = ((long long)n + 1) / 2;
    long long total = 4LL * pairs;
    int blocks = (int)((total + threads - 1) / threads);
    SHEmbed_kernel<<<blocks, threads>>>(y, x, dirs, sh, out, n);
}